// round 11
// baseline (speedup 1.0000x reference)
#include <cuda_runtime.h>
#include <cstddef>

#define FULLMASK 0xffffffffu

// Global scratch (static __device__ arrays - no allocation at runtime)
static __device__ __align__(16) float g_patch[16384 * 784];   // 51.4 MB
static __device__ __align__(16) float g_tok2[16384 * 784];    // 51.4 MB
static __device__ __align__(16) float g_v[16384 * 784];       // 51.4 MB stage1 V
static __device__ __align__(16) float g_v2[16384 * 392];      // 25.7 MB stage2 V
static __device__ __align__(16) float g_wv1[12544];           // WV1 transposed [s][i/4][o][4]
static __device__ __align__(16) float g_wv2[6272];            // WV2 transposed [s][i/4][d][4]
static __device__ __align__(16) float g_vbias[784];           // pos-emb folded V bias
static __device__ unsigned g_ctrA;
static __device__ unsigned g_ctrB;

// ---------------------------------------------------------------------------
// Kernel P: grayscale + patch scatter (4 px/thread) + weight transposes +
// V-bias fold + counter reset.
// ---------------------------------------------------------------------------
__global__ void vitP(const float* __restrict__ x,
                     const float* __restrict__ pe,
                     const float* __restrict__ WV1,
                     const float* __restrict__ WV2)
{
    int t = blockIdx.x * 256 + threadIdx.x;
    if (t == 0) { g_ctrA = 0; g_ctrB = 0; }
    if (t < 12544) {
        int s = t >> 8, r = t & 255, i = r >> 4, o = r & 15;
        g_wv1[s * 256 + (i >> 2) * 64 + o * 4 + (i & 3)] = WV1[(s * 16 + o) * 32 + i];
    }
    if (t < 6272) {
        int s = t >> 7, r = t & 127, i = r >> 3, d = r & 7;
        g_wv2[s * 128 + (i >> 2) * 32 + d * 4 + (i & 3)] = WV2[(s * 8 + d) * 16 + i];
    }
    if (t < 784) {
        int s = t >> 4, o = t & 15;
        const float* gw = WV1 + (s * 16 + o) * 32 + 16;
        const float* pp = pe + s * 16;
        float acc = 0.f;
#pragma unroll
        for (int j = 0; j < 16; ++j) acc = fmaf(pp[j], gw[j], acc);
        g_vbias[t] = acc;
    }
    if (t >= 16384 * 196) return;
    int b = t / 196;
    int r = t - b * 196;          // py*7 + sx
    int py = r / 7;
    int sx = r - py * 7;
    const float4* xb = (const float4*)(x + (size_t)b * 2352);
    int off = py * 7 + sx;
    float4 c0 = __ldg(xb + off);
    float4 c1 = __ldg(xb + 196 + off);
    float4 c2 = __ldg(xb + 392 + off);
    float4 g;
    g.x = 0.299f * c0.x + 0.587f * c1.x + 0.114f * c2.x;
    g.y = 0.299f * c0.y + 0.587f * c1.y + 0.114f * c2.y;
    g.z = 0.299f * c0.z + 0.587f * c1.z + 0.114f * c2.z;
    g.w = 0.299f * c0.w + 0.587f * c1.w + 0.114f * c2.w;
    int patch = (py >> 2) * 7 + sx;
    *(float4*)(g_patch + (size_t)b * 784 + patch * 16 + (py & 3) * 4) = g;
}

// 16 FMAs of a float4-quad weight block against patch quads p0..p3
#define FMA16(acc0, acc1, W0, W1, W2, W3)                                   \
    acc0 = fmaf(p0.x, W0.x, acc0); acc1 = fmaf(p0.y, W0.y, acc1);           \
    acc0 = fmaf(p0.z, W0.z, acc0); acc1 = fmaf(p0.w, W0.w, acc1);           \
    acc0 = fmaf(p1.x, W1.x, acc0); acc1 = fmaf(p1.y, W1.y, acc1);           \
    acc0 = fmaf(p1.z, W1.z, acc0); acc1 = fmaf(p1.w, W1.w, acc1);           \
    acc0 = fmaf(p2.x, W2.x, acc0); acc1 = fmaf(p2.y, W2.y, acc1);           \
    acc0 = fmaf(p2.z, W2.z, acc0); acc1 = fmaf(p2.w, W2.w, acc1);           \
    acc0 = fmaf(p3.x, W3.x, acc0); acc1 = fmaf(p3.y, W3.y, acc1);           \
    acc0 = fmaf(p3.z, W3.z, acc0); acc1 = fmaf(p3.w, W3.w, acc1);

// ---------------------------------------------------------------------------
// Kernel A (stage 1): Q,K weights in SMEM; V weights/bias from global (L1/L2).
// Half-warp = 1 element, per-half atomic counter (granularity 1).
// 384 threads, 2 CTAs/SM.
// SMEM: 2*12544 + 2*784 + 12*64 = 27424 floats = 109696 B.
// ---------------------------------------------------------------------------
__global__ void __launch_bounds__(384, 2) vitA(
    const float* __restrict__ pe,
    const float* __restrict__ WQ1,
    const float* __restrict__ WK1)
{
    extern __shared__ float sm[];
    float* sW = sm;          // Q at 0, K at 12544
    float* sB = sm + 25088;  // Q,K biases
    float* sKV = sm + 26656; // 12 warps * 64

    const int tid = threadIdx.x;
    {
        const float* Wg[2] = {WQ1, WK1};
        for (int w = 0; w < 2; ++w) {
            const float* G = Wg[w];
            float* dst = sW + w * 12544;
            for (int idx = tid; idx < 12544; idx += 384) {
                int s = idx >> 8, r = idx & 255, i = r >> 4, o = r & 15;
                dst[s * 256 + (i >> 2) * 64 + o * 4 + (i & 3)] = G[(s * 16 + o) * 32 + i];
            }
            float* db = sB + w * 784;
            for (int idx = tid; idx < 784; idx += 384) {
                int s = idx >> 4, o = idx & 15;
                const float* gw = G + (s * 16 + o) * 32 + 16;
                const float* pp = pe + s * 16;
                float acc = 0.f;
#pragma unroll
                for (int j = 0; j < 16; ++j) acc = fmaf(pp[j], gw[j], acc);
                db[idx] = acc;
            }
        }
    }
    __syncthreads();

    const int warpId = tid >> 5;
    const int lane = tid & 31;
    const int hh = lane >> 4;
    const int l16 = lane & 15;
    float* kb = sKV + warpId * 64;   // [buf 0/1][lane]

    for (;;) {
        unsigned p;
        if ((lane & 15) == 0) p = atomicAdd(&g_ctrA, 1u);
        p = __shfl_sync(FULLMASK, p, hh << 4);
        if (__all_sync(FULLMASK, p >= 16384u)) break;
        const bool valid = p < 16384u;
        const int elem = valid ? (int)p : 0;
        const float* pb = g_patch + (size_t)elem * 784;
        float* vb = g_v + (size_t)elem * 784;

        float S[16];
#pragma unroll
        for (int e = 0; e < 16; ++e) S[e] = 0.f;

        int cur = 0;
        const float4* pv = (const float4*)pb;
        float4 p0 = __ldg(pv + 0), p1 = __ldg(pv + 1);
        float4 p2 = __ldg(pv + 2), p3 = __ldg(pv + 3);

        // ---- pass 1: q,k,v per s; gram S; store v ----
#pragma unroll 1
        for (int s = 0; s < 49; ++s) {
            int sn = (s < 48) ? s + 1 : 48;
            float4 n0 = __ldg(pv + sn * 4 + 0), n1 = __ldg(pv + sn * 4 + 1);
            float4 n2 = __ldg(pv + sn * 4 + 2), n3 = __ldg(pv + sn * 4 + 3);

            // V weights early (L1/L2): overlap with q/k LDS+FMA below
            const float4* wv4 = (const float4*)(g_wv1 + s * 256 + l16 * 4);
            float4 c0 = __ldg(wv4 + 0), c1 = __ldg(wv4 + 16);
            float4 c2 = __ldg(wv4 + 32), c3 = __ldg(wv4 + 48);
            float vbias = __ldg(g_vbias + s * 16 + l16);

            const float4* wq4 = (const float4*)(sW + s * 256 + l16 * 4);
            float4 a0 = wq4[0], a1 = wq4[16], a2 = wq4[32], a3 = wq4[48];
            float q0 = sB[s * 16 + l16], q1 = 0.f;
            FMA16(q0, q1, a0, a1, a2, a3);

            const float4* wk4 = (const float4*)(sW + 12544 + s * 256 + l16 * 4);
            float4 b0 = wk4[0], b1 = wk4[16], b2 = wk4[32], b3 = wk4[48];
            float k0 = sB[784 + s * 16 + l16], k1 = 0.f;
            FMA16(k0, k1, b0, b1, b2, b3);

            float w0 = vbias, w1 = 0.f;
            FMA16(w0, w1, c0, c1, c2, c3);
            if (valid) vb[s * 16 + l16] = w0 + w1;   // store v

            float q = q0 + q1;
            kb[cur * 32 + lane] = k0 + k1;
            __syncwarp();
            const float4* kv4 = (const float4*)(kb + cur * 32 + hh * 16);
            float4 v0 = kv4[0], v1 = kv4[1], v2 = kv4[2], v3 = kv4[3];
            S[0] = fmaf(q, v0.x, S[0]);  S[1] = fmaf(q, v0.y, S[1]);
            S[2] = fmaf(q, v0.z, S[2]);  S[3] = fmaf(q, v0.w, S[3]);
            S[4] = fmaf(q, v1.x, S[4]);  S[5] = fmaf(q, v1.y, S[5]);
            S[6] = fmaf(q, v1.z, S[6]);  S[7] = fmaf(q, v1.w, S[7]);
            S[8] = fmaf(q, v2.x, S[8]);  S[9] = fmaf(q, v2.y, S[9]);
            S[10] = fmaf(q, v2.z, S[10]); S[11] = fmaf(q, v2.w, S[11]);
            S[12] = fmaf(q, v3.x, S[12]); S[13] = fmaf(q, v3.y, S[13]);
            S[14] = fmaf(q, v3.z, S[14]); S[15] = fmaf(q, v3.w, S[15]);
            cur ^= 1;
            p0 = n0; p1 = n1; p2 = n2; p3 = n3;
        }
#pragma unroll
        for (int e = 0; e < 16; ++e) S[e] *= (1.f / 7.f);

        __syncwarp();  // v stores visible to all lanes of the warp

        // ---- pass 2: read v, apply S, softmax(16) -> tok2 ----
        float* ob = g_tok2 + (size_t)elem * 784;
        const float4* vv = (const float4*)vb;
        float4 u0 = vv[0], u1 = vv[1], u2 = vv[2], u3 = vv[3];
#pragma unroll 1
        for (int s = 0; s < 49; ++s) {
            int sn = (s < 48) ? s + 1 : 48;
            float4 n0 = vv[sn * 4 + 0], n1 = vv[sn * 4 + 1];
            float4 n2 = vv[sn * 4 + 2], n3 = vv[sn * 4 + 3];

            float o = 0.f;
            o = fmaf(S[0], u0.x, o);  o = fmaf(S[1], u0.y, o);
            o = fmaf(S[2], u0.z, o);  o = fmaf(S[3], u0.w, o);
            o = fmaf(S[4], u1.x, o);  o = fmaf(S[5], u1.y, o);
            o = fmaf(S[6], u1.z, o);  o = fmaf(S[7], u1.w, o);
            o = fmaf(S[8], u2.x, o);  o = fmaf(S[9], u2.y, o);
            o = fmaf(S[10], u2.z, o); o = fmaf(S[11], u2.w, o);
            o = fmaf(S[12], u3.x, o); o = fmaf(S[13], u3.y, o);
            o = fmaf(S[14], u3.z, o); o = fmaf(S[15], u3.w, o);

            float m = o;
#pragma unroll
            for (int dd = 8; dd; dd >>= 1)
                m = fmaxf(m, __shfl_xor_sync(FULLMASK, m, dd, 16));
            float ex = __expf(o - m);
            float sum = ex;
#pragma unroll
            for (int dd = 8; dd; dd >>= 1)
                sum += __shfl_xor_sync(FULLMASK, sum, dd, 16);
            if (valid) ob[s * 16 + l16] = __fdividef(ex, sum);
            u0 = n0; u1 = n1; u2 = n2; u3 = n3;
        }
    }
}

// ---------------------------------------------------------------------------
// Kernel B: Q,K weights in SMEM; V from global. Octet = 1 element, per-octet
// atomic counter. fc1 fused. 384 threads, 2 CTAs/SM.
// SMEM: 2*6272 + 6272 + 160 + 32 + 12*64 + 12*64 = 20544 floats = 82176 B.
// ---------------------------------------------------------------------------
__global__ void __launch_bounds__(384, 2) vitB(
    const float* __restrict__ WQ2,
    const float* __restrict__ WK2,
    const float* __restrict__ f1w,
    const float* __restrict__ f1b,
    const float* __restrict__ f2w,
    const float* __restrict__ f2b,
    float* __restrict__ out)
{
    extern __shared__ float sm[];
    float* sW2 = sm;            // Q at 0, K at 6272
    float* sF1t = sm + 12544;   // 6272 : [d8][s][j]
    float* sF2 = sm + 18816;    // 160
    float* sB1 = sm + 18976;    // 16
    float* sB2 = sm + 18992;    // 16
    float* sKV = sm + 19008;    // 12 * 64
    float* sHB = sm + 19776;    // 12 * 64

    const int tid = threadIdx.x;
    {
        const float* Wg[2] = {WQ2, WK2};
        for (int w = 0; w < 2; ++w) {
            const float* G = Wg[w];
            float* dst = sW2 + w * 6272;
            for (int idx = tid; idx < 6272; idx += 384) {
                int s = idx >> 7, r = idx & 127, i = r >> 3, d = r & 7;
                dst[s * 128 + (i >> 2) * 32 + d * 4 + (i & 3)] = G[(s * 8 + d) * 16 + i];
            }
        }
        for (int idx = tid; idx < 6272; idx += 384) {
            int d = idx / 784, r = idx - d * 784, s = r >> 4, j = r & 15;
            sF1t[(d * 49 + s) * 16 + j] = f1w[j * 392 + s * 8 + d];
        }
        for (int idx = tid; idx < 160; idx += 384) {
            int j = idx / 10, c = idx - j * 10;
            sF2[idx] = f2w[c * 16 + j];
        }
        if (tid < 16) sB1[tid] = f1b[tid];
        if (tid < 10) sB2[tid] = f2b[tid];
    }
    __syncthreads();

    const int warpId = tid >> 5;
    const int lane = tid & 31;
    const int oct = lane >> 3;   // octet id
    const int d8 = lane & 7;     // output dim
    float* kb = sKV + warpId * 64;
    float* hb = sHB + warpId * 64;

    for (;;) {
        unsigned p;
        if ((lane & 7) == 0) p = atomicAdd(&g_ctrB, 1u);
        p = __shfl_sync(FULLMASK, p, oct << 3);
        if (__all_sync(FULLMASK, p >= 16384u)) break;
        const bool valid = p < 16384u;
        const int elem = valid ? (int)p : 0;
        const float* tb = g_tok2 + (size_t)elem * 784;
        float* vb = g_v2 + (size_t)elem * 392;

        float S2[8];
#pragma unroll
        for (int e = 0; e < 8; ++e) S2[e] = 0.f;

        int cur = 0;
        const float4* pv = (const float4*)tb;
        float4 p0 = __ldg(pv + 0), p1 = __ldg(pv + 1);
        float4 p2 = __ldg(pv + 2), p3 = __ldg(pv + 3);

        // ---- pass 1: q2,k2,v2 per s; gram; store v2 ----
#pragma unroll 1
        for (int s = 0; s < 49; ++s) {
            int sn = (s < 48) ? s + 1 : 48;
            float4 n0 = __ldg(pv + sn * 4 + 0), n1 = __ldg(pv + sn * 4 + 1);
            float4 n2 = __ldg(pv + sn * 4 + 2), n3 = __ldg(pv + sn * 4 + 3);

            const float4* wv4 = (const float4*)(g_wv2 + s * 128 + d8 * 4);
            float4 c0 = __ldg(wv4 + 0), c1 = __ldg(wv4 + 8);
            float4 c2 = __ldg(wv4 + 16), c3 = __ldg(wv4 + 24);

            const float4* wq4 = (const float4*)(sW2 + s * 128 + d8 * 4);
            float4 a0 = wq4[0], a1 = wq4[8], a2 = wq4[16], a3 = wq4[24];
            float q0 = 0.f, q1 = 0.f;
            FMA16(q0, q1, a0, a1, a2, a3);

            const float4* wk4 = (const float4*)(sW2 + 6272 + s * 128 + d8 * 4);
            float4 b0 = wk4[0], b1 = wk4[8], b2 = wk4[16], b3 = wk4[24];
            float k0 = 0.f, k1 = 0.f;
            FMA16(k0, k1, b0, b1, b2, b3);

            float w0 = 0.f, w1 = 0.f;
            FMA16(w0, w1, c0, c1, c2, c3);
            if (valid) vb[s * 8 + d8] = w0 + w1;    // store v2

            float q = q0 + q1;
            kb[cur * 32 + lane] = k0 + k1;
            __syncwarp();
            const float4* kv4 = (const float4*)(kb + cur * 32 + oct * 8);
            float4 v0 = kv4[0], v1 = kv4[1];
            S2[0] = fmaf(q, v0.x, S2[0]); S2[1] = fmaf(q, v0.y, S2[1]);
            S2[2] = fmaf(q, v0.z, S2[2]); S2[3] = fmaf(q, v0.w, S2[3]);
            S2[4] = fmaf(q, v1.x, S2[4]); S2[5] = fmaf(q, v1.y, S2[5]);
            S2[6] = fmaf(q, v1.z, S2[6]); S2[7] = fmaf(q, v1.w, S2[7]);
            cur ^= 1;
            p0 = n0; p1 = n1; p2 = n2; p3 = n3;
        }
#pragma unroll
        for (int e = 0; e < 8; ++e) S2[e] *= (1.f / 7.f);

        __syncwarp();  // v2 stores visible warp-wide

        // ---- pass 2: read v2, apply S2, softmax(8), fc1 fused ----
        float h[16];
#pragma unroll
        for (int j = 0; j < 16; ++j) h[j] = 0.f;

        const float4* vv = (const float4*)vb;
        float4 u0 = vv[0], u1 = vv[1];
#pragma unroll 1
        for (int s = 0; s < 49; ++s) {
            int sn = (s < 48) ? s + 1 : 48;
            float4 n0 = vv[sn * 2 + 0], n1 = vv[sn * 2 + 1];

            float o = 0.f;
            o = fmaf(S2[0], u0.x, o); o = fmaf(S2[1], u0.y, o);
            o = fmaf(S2[2], u0.z, o); o = fmaf(S2[3], u0.w, o);
            o = fmaf(S2[4], u1.x, o); o = fmaf(S2[5], u1.y, o);
            o = fmaf(S2[6], u1.z, o); o = fmaf(S2[7], u1.w, o);

            float m = o;
#pragma unroll
            for (int dd = 4; dd; dd >>= 1)
                m = fmaxf(m, __shfl_xor_sync(FULLMASK, m, dd, 8));
            float ex = __expf(o - m);
            float sum = ex;
#pragma unroll
            for (int dd = 4; dd; dd >>= 1)
                sum += __shfl_xor_sync(FULLMASK, sum, dd, 8);
            float tv = __fdividef(ex, sum);   // tok3[s][d8]

            const float4* wt = (const float4*)(sF1t + (d8 * 49 + s) * 16);
            float4 f0 = wt[0], f1 = wt[1], f2 = wt[2], f3 = wt[3];
            h[0] = fmaf(tv, f0.x, h[0]);  h[1] = fmaf(tv, f0.y, h[1]);
            h[2] = fmaf(tv, f0.z, h[2]);  h[3] = fmaf(tv, f0.w, h[3]);
            h[4] = fmaf(tv, f1.x, h[4]);  h[5] = fmaf(tv, f1.y, h[5]);
            h[6] = fmaf(tv, f1.z, h[6]);  h[7] = fmaf(tv, f1.w, h[7]);
            h[8] = fmaf(tv, f2.x, h[8]);  h[9] = fmaf(tv, f2.y, h[9]);
            h[10] = fmaf(tv, f2.z, h[10]); h[11] = fmaf(tv, f2.w, h[11]);
            h[12] = fmaf(tv, f3.x, h[12]); h[13] = fmaf(tv, f3.y, h[13]);
            h[14] = fmaf(tv, f3.z, h[14]); h[15] = fmaf(tv, f3.w, h[15]);
            u0 = n0; u1 = n1;
        }

        // split-butterfly reduce over the 8 octet lanes: 14 shfl total
#pragma unroll
        for (int j = 0; j < 8; ++j) {
            float sendv = (d8 & 1) ? h[j] : h[j + 8];
            float keep  = (d8 & 1) ? h[j + 8] : h[j];
            h[j] = keep + __shfl_xor_sync(FULLMASK, sendv, 1, 8);
        }
#pragma unroll
        for (int j = 0; j < 4; ++j) {
            float sendv = (d8 & 2) ? h[j] : h[j + 4];
            float keep  = (d8 & 2) ? h[j + 4] : h[j];
            h[j] = keep + __shfl_xor_sync(FULLMASK, sendv, 2, 8);
        }
#pragma unroll
        for (int j = 0; j < 2; ++j) {
            float sendv = (d8 & 4) ? h[j] : h[j + 2];
            float keep  = (d8 & 4) ? h[j + 2] : h[j];
            h[j] = keep + __shfl_xor_sync(FULLMASK, sendv, 4, 8);
        }
        int ja = 8 * (d8 & 1) + 4 * ((d8 >> 1) & 1) + 2 * ((d8 >> 2) & 1);
        __syncwarp();
        hb[oct * 16 + ja] = fmaxf(h[0] + sB1[ja], 0.f);
        hb[oct * 16 + ja + 1] = fmaxf(h[1] + sB1[ja + 1], 0.f);
        __syncwarp();

        // ---- fc2 + softmax over 10 (octet-local) ----
        const float* ho = hb + oct * 16;
        int c2 = (d8 < 2) ? (d8 + 8) : 8;
        float lg1 = sB2[d8];
        float lg2 = sB2[c2];
#pragma unroll
        for (int j = 0; j < 16; ++j) {
            float hv = ho[j];
            lg1 = fmaf(hv, sF2[j * 10 + d8], lg1);
            lg2 = fmaf(hv, sF2[j * 10 + c2], lg2);
        }
        float lg2v = (d8 < 2) ? lg2 : -1e30f;
        float m = fmaxf(lg1, lg2v);
#pragma unroll
        for (int dd = 4; dd; dd >>= 1)
            m = fmaxf(m, __shfl_xor_sync(FULLMASK, m, dd, 8));
        float e1 = __expf(lg1 - m);
        float e2 = (d8 < 2) ? __expf(lg2 - m) : 0.f;
        float sum = e1 + e2;
#pragma unroll
        for (int dd = 4; dd; dd >>= 1)
            sum += __shfl_xor_sync(FULLMASK, sum, dd, 8);
        float inv = __fdividef(1.f, sum);
        if (valid) {
            out[elem * 10 + d8] = e1 * inv;
            if (d8 < 2) out[elem * 10 + 8 + d8] = e2 * inv;
        }
        __syncwarp();  // protect hb before next iteration
    }
}

extern "C" void kernel_launch(void* const* d_in, const int* in_sizes, int n_in,
                              void* d_out, int out_size)
{
    (void)in_sizes; (void)n_in; (void)out_size;
    const float* x   = (const float*)d_in[0];
    const float* pe  = (const float*)d_in[1];
    const float* WQ1 = (const float*)d_in[2];
    const float* WK1 = (const float*)d_in[3];
    const float* WV1 = (const float*)d_in[4];
    const float* WQ2 = (const float*)d_in[5];
    const float* WK2 = (const float*)d_in[6];
    const float* WV2 = (const float*)d_in[7];
    const float* f1w = (const float*)d_in[8];
    const float* f1b = (const float*)d_in[9];
    const float* f2w = (const float*)d_in[10];
    const float* f2b = (const float*)d_in[11];
    float* out = (float*)d_out;

    const size_t smA = (size_t)27424 * sizeof(float);  // 109696 B
    const size_t smB = (size_t)20544 * sizeof(float);  // 82176 B
    cudaFuncSetAttribute(vitA, cudaFuncAttributeMaxDynamicSharedMemorySize, (int)smA);
    cudaFuncSetAttribute(vitB, cudaFuncAttributeMaxDynamicSharedMemorySize, (int)smB);

    vitP<<<(16384 * 196 + 255) / 256, 256>>>(x, pe, WV1, WV2);
    vitA<<<296, 384, smA>>>(pe, WQ1, WK1);
    vitB<<<296, 384, smB>>>(WQ2, WK2, f1w, f1b, f2w, f2b, out);
}